// round 17
// baseline (speedup 1.0000x reference)
#include <cuda_runtime.h>
#include <cuda_fp16.h>
#include <cstdint>

// BatchedHGNNLayer: out = diag(Dv^-1/2) H diag(De^-1) H^T diag(Dv^-1/2) x W^T + b
// B=8, N=4096, E=2048, C=128 fp32 in/out.
// FP16 m16n8k16 pipeline, ring-5 unroll-2 mainloops (1 sync / 2 tiles),
// De via single LDS.128 per tile. gemm3 tiles stride-40h (16B-aligned!).

#define B_ 8
#define N_ 4096
#define E_ 2048
#define C_ 128
#define EPS 1e-6f

// ---------------- scratch ----------------------------------------------------
__device__ float  g_DvInv[B_ * N_];
__device__ __half g_Hh[(size_t)B_ * N_ * E_];     // fp16(H)            [b][n][e]
__device__ __half g_Xh[(size_t)B_ * N_ * C_];     // fp16(x * DvInv)    [b][n][c]
__device__ __half g_Wh[C_ * C_];                  // fp16(W)
__device__ __half g_M2Th[(size_t)B_ * C_ * E_];   // fp16((De^-1 H^T Xs) W^T)^T [b][c2][e]

// ---------------- helpers ----------------------------------------------------
__device__ __forceinline__ uint32_t smem_u32(const void* p) {
    uint32_t a;
    asm("{ .reg .u64 t; cvta.to.shared.u64 t, %1; cvt.u32.u64 %0, t; }" : "=r"(a) : "l"(p));
    return a;
}
__device__ __forceinline__ uint32_t h2u(float a, float b) {
    __half2 h = __floats2half2_rn(a, b);
    return *(uint32_t*)&h;
}
__device__ __forceinline__ void mma_f16(float* c, const uint32_t* a, const uint32_t* b) {
    asm volatile(
        "mma.sync.aligned.m16n8k16.row.col.f32.f16.f16.f32 "
        "{%0,%1,%2,%3}, {%4,%5,%6,%7}, {%8,%9}, {%0,%1,%2,%3};"
        : "+f"(c[0]), "+f"(c[1]), "+f"(c[2]), "+f"(c[3])
        : "r"(a[0]), "r"(a[1]), "r"(a[2]), "r"(a[3]), "r"(b[0]), "r"(b[1]));
}
#define CP16(dst, src) \
    asm volatile("cp.async.cg.shared.global [%0], [%1], 16;" :: "r"(dst), "l"(src))
#define CP_COMMIT() asm volatile("cp.async.commit_group;" ::: "memory")
#define CP_WAIT(n)  asm volatile("cp.async.wait_group %0;" :: "n"(n) : "memory")
#define LDSM4(r0, r1, r2, r3, addr)                                             \
    asm volatile("ldmatrix.sync.aligned.m8n8.x4.shared.b16 {%0,%1,%2,%3}, [%4];"\
                 : "=r"(r0), "=r"(r1), "=r"(r2), "=r"(r3) : "r"(addr))
#define LDSM4T(r0, r1, r2, r3, addr)                                            \
    asm volatile("ldmatrix.sync.aligned.m8n8.x4.trans.shared.b16 {%0,%1,%2,%3}, [%4];"\
                 : "=r"(r0), "=r"(r1), "=r"(r2), "=r"(r3) : "r"(addr))

// ---------------- prep kernels ------------------------------------------------
__global__ void prep_h(const float* __restrict__ Hg) {
    int row = blockIdx.x * 8 + threadIdx.y;
    const float4* src = (const float4*)(Hg + (size_t)row * E_);
    uint2* dst = (uint2*)(g_Hh + (size_t)row * E_);
    float s = 0.f;
    for (int i = threadIdx.x; i < E_ / 4; i += 32) {
        float4 v = src[i];
        s += (v.x + v.y) + (v.z + v.w);
        uint2 u; u.x = h2u(v.x, v.y); u.y = h2u(v.z, v.w);
        dst[i] = u;
    }
    #pragma unroll
    for (int o = 16; o; o >>= 1) s += __shfl_xor_sync(0xffffffffu, s, o);
    if (threadIdx.x == 0) g_DvInv[row] = rsqrtf(s + EPS);
}

__global__ void prep_x(const float* __restrict__ xg) {
    int i = blockIdx.x * 256 + threadIdx.x;     // f4 index
    int row = i >> 5;
    float dv = g_DvInv[row];
    float4 v = ((const float4*)xg)[i];
    uint2 u; u.x = h2u(v.x * dv, v.y * dv); u.y = h2u(v.z * dv, v.w * dv);
    ((uint2*)g_Xh)[i] = u;
}

__global__ void prep_w(const float* __restrict__ Wg) {
    int i = blockIdx.x * 256 + threadIdx.x;     // 4096 f4
    float4 v = ((const float4*)Wg)[i];
    uint2 u; u.x = h2u(v.x, v.y); u.y = h2u(v.z, v.w);
    ((uint2*)g_Wh)[i] = u;
}

// ---------------- GEMM1: BM=64, [k][m] fp16, 2 CTAs/SM, ring-5 unroll-2 ------
#define TA1 (32 * 72 * 2)          // 4608 (stride 144B = 9*16 ✓)
#define TB1 (32 * 136 * 2)         // 8704 (stride 272B = 17*16 ✓)
#define DYN1 (5 * (TA1 + TB1))     // 66560

__global__ __launch_bounds__(256, 2) void gemm1_kernel() {
    extern __shared__ __align__(16) char ds[];
    __shared__ float deSm[32][64];   // per-k-row column partials
    __shared__ float scl[64];

    const int tid = threadIdx.x, b = blockIdx.z, blk = blockIdx.x;
    const int lane = tid & 31, wid = tid >> 5;
    const int g = lane >> 2, tg = lane & 3;
    const int wm = wid & 1, wn = wid >> 1;
    const int r8 = lane & 7, q0 = (lane >> 3) & 1, q1 = (lane >> 4) & 1;

    const __half* Ag = g_Hh + (size_t)b * N_ * E_;
    const __half* Bg = g_Xh + (size_t)b * N_ * C_;
    const int acol = blk * 64;

    const uint32_t sA = smem_u32(ds), sB = sA + 5 * TA1;
    const uint32_t offTA = (uint32_t)(((q1 * 8 + r8) * 72 + q0 * 8) * 2);
    const uint32_t offTB = (uint32_t)(((q1 * 8 + r8) * 136 + q0 * 8) * 2);

    float acc[2][4][4];
    #pragma unroll
    for (int i = 0; i < 2; i++)
        #pragma unroll
        for (int j = 0; j < 4; j++)
            #pragma unroll
            for (int rr = 0; rr < 4; rr++) acc[i][j][rr] = 0.f;

    float de8[8];
    #pragma unroll
    for (int j = 0; j < 8; j++) de8[j] = 0.f;
    const int drow = tid >> 3, dchk = tid & 7;

    auto issue = [&](int kt, int buf) {
        {   // A: 32 k-rows x 64m = 256 chunks, 1/thread
            int k = tid >> 3, q = tid & 7;
            CP16(sA + buf * TA1 + (k * 72 + q * 8) * 2,
                 Ag + (size_t)(kt * 32 + k) * E_ + acol + q * 8);
        }
        #pragma unroll
        for (int i = 0; i < 2; i++) {   // B: 32 k-rows x 128c = 512 chunks
            int ch = tid + 256 * i;
            int k = ch >> 4, q = ch & 15;
            CP16(sB + buf * TB1 + (k * 136 + q * 8) * 2,
                 Bg + (size_t)(kt * 32 + k) * C_ + q * 8);
        }
        CP_COMMIT();
    };

    auto compute = [&](int buf) {
        const __half* As = (const __half*)(ds + (size_t)buf * TA1);
        const uint32_t sAb = sA + (uint32_t)buf * TA1;
        const uint32_t sBb = sB + (uint32_t)buf * TB1;

        {   // De: one LDS.128 per thread covers the 32x64 tile exactly once
            uint4 dv4 = *(const uint4*)(As + drow * 72 + dchk * 8);
            const __half2* hp = (const __half2*)&dv4;
            #pragma unroll
            for (int j = 0; j < 4; j++) {
                float2 f = __half22float2(hp[j]);
                de8[2 * j] += f.x; de8[2 * j + 1] += f.y;
            }
        }

        #pragma unroll
        for (int kc = 0; kc < 32; kc += 16) {
            uint32_t af[2][4], bf[4][2];
            #pragma unroll
            for (int mt = 0; mt < 2; mt++) {
                uint32_t addr = sAb + offTA + (uint32_t)((kc * 72 + wm * 32 + mt * 16) * 2);
                LDSM4T(af[mt][0], af[mt][1], af[mt][2], af[mt][3], addr);
            }
            #pragma unroll
            for (int p = 0; p < 2; p++) {
                uint32_t d0, d1, d2, d3;
                uint32_t addr = sBb + offTB + (uint32_t)((kc * 136 + wn * 32 + p * 16) * 2);
                LDSM4T(d0, d1, d2, d3, addr);
                bf[2 * p][0] = d0; bf[2 * p + 1][0] = d1;
                bf[2 * p][1] = d2; bf[2 * p + 1][1] = d3;
            }
            #pragma unroll
            for (int mt = 0; mt < 2; mt++)
                #pragma unroll
                for (int nt = 0; nt < 4; nt++)
                    mma_f16(acc[mt][nt], af[mt], bf[nt]);
        }
    };

    const int KT = N_ / 32;   // 128 tiles, 64 iterations
    issue(0, 0); issue(1, 1); issue(2, 2);

    int cb = 0, ib = 3;
    for (int gi = 0; gi < KT / 2; gi++) {
        int t0 = 2 * gi;
        if (t0 + 2 < KT) CP_WAIT(1);
        else             CP_WAIT(0);
        __syncthreads();                       // one barrier per 2 tiles

        int b0 = cb, b1 = (cb + 1 == 5) ? 0 : cb + 1;
        compute(b0);
        compute(b1);

        if (t0 + 3 < KT) { issue(t0 + 3, ib); ib = (ib + 1 == 5) ? 0 : ib + 1; }
        if (t0 + 4 < KT) { issue(t0 + 4, ib); ib = (ib + 1 == 5) ? 0 : ib + 1; }
        cb += 2; if (cb >= 5) cb -= 5;
    }

    // ---- epilogue: De combine, M->smem fp16, W->smem, sub-GEMM M2T = W M^T ----
    __half* Msm = (__half*)ds;                   // [64][136]h = 17408B (A-region 23040B)
    const uint32_t sM = sA;
    const uint32_t sW = sA + 5 * TA1;            // [128][136]h = 34816B (B-region 43520B)

    #pragma unroll
    for (int j = 0; j < 8; j++) deSm[drow][dchk * 8 + j] = de8[j];
    __syncthreads();                             // all compute done; rings reusable
    {
        #pragma unroll
        for (int i = 0; i < 8; i++) {
            int ch = tid + 256 * i;              // 2048 chunks: 128 rows x 16
            int m = ch >> 4, q = ch & 15;
            CP16(sW + (uint32_t)((m * 136 + q * 8) * 2), g_Wh + (size_t)m * C_ + q * 8);
        }
        CP_COMMIT();
    }
    if (tid < 64) {
        float t = EPS;
        #pragma unroll
        for (int r = 0; r < 32; r++) t += deSm[r][tid];
        scl[tid] = 1.0f / t;
    }
    __syncthreads();

    #pragma unroll
    for (int mt = 0; mt < 2; mt++) {
        int rr = wm * 32 + mt * 16 + g;
        float s0 = scl[rr], s1 = scl[rr + 8];
        #pragma unroll
        for (int nt = 0; nt < 4; nt++) {
            int col = wn * 32 + nt * 8 + tg * 2;
            float* c = acc[mt][nt];
            *(uint32_t*)(Msm + rr * 136 + col)       = h2u(c[0] * s0, c[1] * s0);
            *(uint32_t*)(Msm + (rr + 8) * 136 + col) = h2u(c[2] * s1, c[3] * s1);
        }
    }
    CP_WAIT(0);
    __syncthreads();

    float acc2[4][2][4];
    #pragma unroll
    for (int i = 0; i < 4; i++)
        #pragma unroll
        for (int j = 0; j < 2; j++)
            #pragma unroll
            for (int rr = 0; rr < 4; rr++) acc2[i][j][rr] = 0.f;

    const uint32_t offN = (uint32_t)(((q0 * 8 + r8) * 136 + q1 * 8) * 2);

    #pragma unroll
    for (int kc = 0; kc < 128; kc += 16) {
        uint32_t af[4][4], bf[2][2];
        #pragma unroll
        for (int mt = 0; mt < 4; mt++) {
            uint32_t addr = sW + offN + (uint32_t)(((wm * 64 + mt * 16) * 136 + kc) * 2);
            LDSM4(af[mt][0], af[mt][1], af[mt][2], af[mt][3], addr);
        }
        {
            uint32_t d0, d1, d2, d3;
            uint32_t addr = sM + offN + (uint32_t)((wn * 16 * 136 + kc) * 2);
            LDSM4(d0, d1, d2, d3, addr);
            bf[0][0] = d0; bf[1][0] = d1;
            bf[0][1] = d2; bf[1][1] = d3;
        }
        #pragma unroll
        for (int mt = 0; mt < 4; mt++)
            #pragma unroll
            for (int nt = 0; nt < 2; nt++)
                mma_f16(acc2[mt][nt], af[mt], bf[nt]);
    }

    #pragma unroll
    for (int mt = 0; mt < 4; mt++) {
        int c2 = wm * 64 + mt * 16 + g;
        #pragma unroll
        for (int nt = 0; nt < 2; nt++) {
            int e = wn * 16 + nt * 8 + tg * 2;
            float* c = acc2[mt][nt];
            *(uint32_t*)(g_M2Th + ((size_t)b * C_ + c2) * E_ + blk * 64 + e) =
                h2u(c[0], c[1]);
            *(uint32_t*)(g_M2Th + ((size_t)b * C_ + c2 + 8) * E_ + blk * 64 + e) =
                h2u(c[2], c[3]);
        }
    }
}

// ---------------- GEMM3: [m][k] fp16 both, stride-40h, ring-5 unroll-2 -------
#define T3 (128 * 40 * 2)          // 10240 per tile (stride 80B = 5*16 ✓)
#define DYN3 (5 * 2 * T3)          // 102400

__global__ __launch_bounds__(256, 2) void gemm3_kernel(const float* __restrict__ biasg,
                                                       float* __restrict__ Og) {
    extern __shared__ __align__(16) char ds[];
    __shared__ float scl[128];

    const int tid = threadIdx.x, b = blockIdx.z, blk = blockIdx.x;
    const int lane = tid & 31, wid = tid >> 5;
    const int g = lane >> 2, tg = lane & 3;
    const int wm = wid & 1, wn = wid >> 1;
    const int r8 = lane & 7, q0 = (lane >> 3) & 1, q1 = (lane >> 4) & 1;

    const __half* Ag = g_Hh + ((size_t)b * N_ + blk * 128) * E_;
    const __half* Bg = g_M2Th + (size_t)b * C_ * E_;

    if (tid < 128) scl[tid] = biasg[tid];

    const uint32_t sA = smem_u32(ds), sB = sA + 5 * T3;
    const uint32_t offN = (uint32_t)(((q0 * 8 + r8) * 40 + q1 * 8) * 2);

    float acc[4][4][4];
    #pragma unroll
    for (int i = 0; i < 4; i++)
        #pragma unroll
        for (int j = 0; j < 4; j++)
            #pragma unroll
            for (int rr = 0; rr < 4; rr++) acc[i][j][rr] = 0.f;

    auto issue = [&](int kt, int buf) {
        #pragma unroll
        for (int i = 0; i < 2; i++) {
            int ch = tid + 256 * i;            // 512 chunks: 128 rows x 4
            int m = ch >> 2, q = ch & 3;
            CP16(sA + buf * T3 + (m * 40 + q * 8) * 2,
                 Ag + (size_t)m * E_ + kt * 32 + q * 8);
            CP16(sB + buf * T3 + (m * 40 + q * 8) * 2,
                 Bg + (size_t)m * E_ + kt * 32 + q * 8);
        }
        CP_COMMIT();
    };

    auto compute = [&](int buf) {
        const uint32_t sAb = sA + (uint32_t)buf * T3;
        const uint32_t sBb = sB + (uint32_t)buf * T3;
        #pragma unroll
        for (int kc = 0; kc < 32; kc += 16) {
            uint32_t af[4][4], bf[4][2];
            #pragma unroll
            for (int mt = 0; mt < 4; mt++) {
                uint32_t addr = sAb + offN + (uint32_t)(((wm * 64 + mt * 16) * 40 + kc) * 2);
                LDSM4(af[mt][0], af[mt][1], af[mt][2], af[mt][3], addr);
            }
            #pragma unroll
            for (int p = 0; p < 2; p++) {
                uint32_t d0, d1, d2, d3;
                uint32_t addr = sBb + offN + (uint32_t)(((wn * 32 + p * 16) * 40 + kc) * 2);
                LDSM4(d0, d1, d2, d3, addr);
                bf[2 * p][0] = d0; bf[2 * p + 1][0] = d1;
                bf[2 * p][1] = d2; bf[2 * p + 1][1] = d3;
            }
            #pragma unroll
            for (int mt = 0; mt < 4; mt++)
                #pragma unroll
                for (int nt = 0; nt < 4; nt++)
                    mma_f16(acc[mt][nt], af[mt], bf[nt]);
        }
    };

    const int KT = E_ / 32;   // 64 tiles, 32 iterations
    issue(0, 0); issue(1, 1); issue(2, 2);

    int cb = 0, ib = 3;
    for (int gi = 0; gi < KT / 2; gi++) {
        int t0 = 2 * gi;
        if (t0 + 2 < KT) CP_WAIT(1);
        else             CP_WAIT(0);
        __syncthreads();

        int b0 = cb, b1 = (cb + 1 == 5) ? 0 : cb + 1;
        compute(b0);
        compute(b1);

        if (t0 + 3 < KT) { issue(t0 + 3, ib); ib = (ib + 1 == 5) ? 0 : ib + 1; }
        if (t0 + 4 < KT) { issue(t0 + 4, ib); ib = (ib + 1 == 5) ? 0 : ib + 1; }
        cb += 2; if (cb >= 5) cb -= 5;
    }

    #pragma unroll
    for (int mt = 0; mt < 4; mt++) {
        int rr = wm * 64 + mt * 16 + g;
        float s0 = g_DvInv[b * N_ + blk * 128 + rr];
        float s1 = g_DvInv[b * N_ + blk * 128 + rr + 8];
        #pragma unroll
        for (int nt = 0; nt < 4; nt++) {
            int col = wn * 32 + nt * 8 + tg * 2;
            float b0 = scl[col], b1 = scl[col + 1];
            float* c = acc[mt][nt];
            *(float2*)(Og + ((size_t)b * N_ + blk * 128 + rr) * C_ + col) =
                make_float2(c[0] * s0 + b0, c[1] * s0 + b1);
            *(float2*)(Og + ((size_t)b * N_ + blk * 128 + rr + 8) * C_ + col) =
                make_float2(c[2] * s1 + b0, c[3] * s1 + b1);
        }
    }
}

// ---------------- launch -----------------------------------------------------
extern "C" void kernel_launch(void* const* d_in, const int* in_sizes, int n_in,
                              void* d_out, int out_size) {
    const float *x = nullptr, *H = nullptr, *W = nullptr, *bias = nullptr;
    for (int i = 0; i < n_in; i++) {
        long long s = in_sizes[i];
        if (s == (long long)B_ * N_ * E_)      H = (const float*)d_in[i];
        else if (s == (long long)B_ * N_ * C_) x = (const float*)d_in[i];
        else if (s == (long long)C_ * C_)      W = (const float*)d_in[i];
        else if (s == (long long)C_)           bias = (const float*)d_in[i];
    }
    float* outp = (float*)d_out;

    cudaFuncSetAttribute(gemm1_kernel, cudaFuncAttributeMaxDynamicSharedMemorySize, DYN1);
    cudaFuncSetAttribute(gemm3_kernel, cudaFuncAttributeMaxDynamicSharedMemorySize, DYN3);

    prep_h<<<B_ * N_ / 8, dim3(32, 8)>>>(H);               // Hh + Dv
    prep_x<<<(B_ * N_ * C_ / 4) / 256, 256>>>(x);          // Xh
    prep_w<<<(C_ * C_ / 4) / 256, 256>>>(W);               // Wh

    // M2Th = W (De^-1 H^T (Dv^-1/2 x))^T   [gemm1 + fused De + fused linear]
    gemm1_kernel<<<dim3(E_ / 64, 1, B_), 256, DYN1>>>();
    // out = Dv^-1/2 (H M2) + bias
    gemm3_kernel<<<dim3(N_ / 128, 1, B_), 256, DYN3>>>(bias, outp);
}